// round 3
// baseline (speedup 1.0000x reference)
#include <cuda_runtime.h>
#include <cstdint>

#define NPTS   32768
#define DDIM   64
#define KCODES 8192
#define MT     128       // rows per CTA
#define NT     128       // codes per tile

// ---------------- device scratch (no allocation allowed) --------------------
__device__ float  g_zT[DDIM * NPTS];    // z transposed  [64][32768], 8 MB
__device__ float  g_eT[DDIM * KCODES];  // emb transposed [64][8192], 2 MB
__device__ float  g_zz[NPTS];
__device__ float  g_ee[KCODES];
__device__ int    g_idx[NPTS];
__device__ double g_loss;

// ---------------- packed f32x2 helpers --------------------------------------
#define FMA_F32X2(d, a, b) \
    asm("fma.rn.f32x2 %0, %1, %2, %0;" : "+l"(d) : "l"(a), "l"(b))
#define SPLAT2(d, x) \
    asm("mov.b64 %0, {%1, %1};" : "=l"(d) : "r"(__float_as_uint(x)))
#define UNPACK2(lo, hi, v) \
    asm("mov.b64 {%0, %1}, %2;" : "=r"(lo), "=r"(hi) : "l"(v))

// ---------------- 1) norms (+ loss reset) ------------------------------------
// zz MUST be the sequential fp32 sum over the 64 features (matches XLA reduce
// rounding closely enough that the final 64-scale quantization buckets agree).
__global__ void vq_norms(const float* __restrict__ z, const float* __restrict__ e) {
    int t = blockIdx.x * blockDim.x + threadIdx.x;
    if (t == 0) g_loss = 0.0;
    if (t < NPTS) {
        const float* p = z + (size_t)t * DDIM;
        float s = 0.f;
        for (int k = 0; k < DDIM; k++) s = __fadd_rn(s, __fmul_rn(p[k], p[k]));
        g_zz[t] = s;
    } else if (t < NPTS + KCODES) {
        const float* p = e + (size_t)(t - NPTS) * DDIM;
        float s = 0.f;
        for (int k = 0; k < DDIM; k++) s = __fadd_rn(s, __fmul_rn(p[k], p[k]));
        g_ee[t - NPTS] = s;
    }
}

// ---------------- 2) transpose [R][C] -> [C][R] ------------------------------
__global__ void vq_transpose(const float* __restrict__ in, float* __restrict__ out,
                             int R, int C) {
    __shared__ float tile[32][33];
    int x = blockIdx.x * 32 + threadIdx.x;  // col in `in`
    int y = blockIdx.y * 32 + threadIdx.y;  // row in `in`
    #pragma unroll
    for (int j = 0; j < 32; j += 8)
        if (x < C && (y + j) < R)
            tile[threadIdx.y + j][threadIdx.x] = in[(size_t)(y + j) * C + x];
    __syncthreads();
    int xo = blockIdx.y * 32 + threadIdx.x;  // row in `in` (col of out-row)
    int yo = blockIdx.x * 32 + threadIdx.y;  // col in `in` (row of out)
    #pragma unroll
    for (int j = 0; j < 32; j += 8)
        if (xo < R && (yo + j) < C)
            out[(size_t)(yo + j) * R + xo] = tile[threadIdx.x][threadIdx.y + j];
}

// ---------------- 3) main: distance GEMM + fused argmin ----------------------
// 256 threads (16x16). Thread tile = 8 rows x 8 codes, codes as 4 f32x2 pairs.
__global__ void __launch_bounds__(256, 2)
vq_main() {
    extern __shared__ float sm[];
    float* z_s  = sm;                 // [64][128]
    float* e_s  = sm + 64 * 128;      // [64][128]
    float* zz_s = sm + 2 * 64 * 128;  // [128]
    float* ee_s = zz_s + 128;         // [128]
    // reduction buffers alias e_s after the tile loop:
    float* rv = e_s;                  // [128][16]
    int*   ri = (int*)(e_s + 128 * 16);

    const int tid  = threadIdx.x;
    const int trow = tid >> 4;        // 0..15
    const int tcol = tid & 15;        // 0..15
    const int row0 = blockIdx.x * MT;

    // load z tile (k-major), conflict-free float4
    for (int i = tid; i < 64 * 32; i += 256) {
        int k = i >> 5, c4 = i & 31;
        ((float4*)z_s)[k * 32 + c4] =
            ((const float4*)(g_zT + (size_t)k * NPTS + row0))[c4];
    }
    if (tid < 128) zz_s[tid] = g_zz[row0 + tid];

    float bv[8]; int bi[8];
    #pragma unroll
    for (int r = 0; r < 8; r++) { bv[r] = 3.4e38f; bi[r] = 0; }

    for (int tile = 0; tile < KCODES / NT; tile++) {
        const int col0 = tile * NT;
        __syncthreads();
        for (int i = tid; i < 64 * 32; i += 256) {
            int k = i >> 5, c4 = i & 31;
            ((float4*)e_s)[k * 32 + c4] =
                ((const float4*)(g_eT + (size_t)k * KCODES + col0))[c4];
        }
        if (tid < 128) ee_s[tid] = g_ee[col0 + tid];
        __syncthreads();

        unsigned long long acc[8][4];
        #pragma unroll
        for (int r = 0; r < 8; r++)
            #pragma unroll
            for (int c = 0; c < 4; c++) acc[r][c] = 0ull;

        const float* zp = z_s + trow * 8;
        const float* ep = e_s + tcol * 8;
        #pragma unroll 4
        for (int k = 0; k < DDIM; k++) {
            union { float4 f; unsigned long long u[2]; } ea, eb;
            float4 za = *(const float4*)(zp + k * 128);
            float4 zb = *(const float4*)(zp + k * 128 + 4);
            ea.f = *(const float4*)(ep + k * 128);
            eb.f = *(const float4*)(ep + k * 128 + 4);
            float zr[8] = {za.x, za.y, za.z, za.w, zb.x, zb.y, zb.z, zb.w};
            #pragma unroll
            for (int r = 0; r < 8; r++) {
                unsigned long long zs;
                SPLAT2(zs, zr[r]);
                FMA_F32X2(acc[r][0], zs, ea.u[0]);
                FMA_F32X2(acc[r][1], zs, ea.u[1]);
                FMA_F32X2(acc[r][2], zs, eb.u[0]);
                FMA_F32X2(acc[r][3], zs, eb.u[1]);
            }
        }
        // epilogue: d = fl( fl(zz+ee) - 2*dot ), strict < keeps lowest index
        #pragma unroll
        for (int r = 0; r < 8; r++) {
            float zzr = zz_s[trow * 8 + r];
            #pragma unroll
            for (int cp = 0; cp < 4; cp++) {
                unsigned int ulo, uhi;
                UNPACK2(ulo, uhi, acc[r][cp]);
                float dlo = __uint_as_float(ulo), dhi = __uint_as_float(uhi);
                int j0 = col0 + tcol * 8 + cp * 2;
                float t0 = __fadd_rn(zzr, ee_s[tcol * 8 + cp * 2]);
                float t1 = __fadd_rn(zzr, ee_s[tcol * 8 + cp * 2 + 1]);
                float d0 = __fmaf_rn(-2.f, dlo, t0);
                float d1 = __fmaf_rn(-2.f, dhi, t1);
                if (d0 < bv[r]) { bv[r] = d0; bi[r] = j0; }
                if (d1 < bv[r]) { bv[r] = d1; bi[r] = j0 + 1; }
            }
        }
    }

    __syncthreads();
    #pragma unroll
    for (int r = 0; r < 8; r++) {
        rv[(trow * 8 + r) * 16 + tcol] = bv[r];
        ri[(trow * 8 + r) * 16 + tcol] = bi[r];
    }
    __syncthreads();
    if (tid < 128) {
        float best = rv[tid * 16]; int besti = ri[tid * 16];
        for (int c = 1; c < 16; c++) {
            float v = rv[tid * 16 + c]; int ix = ri[tid * 16 + c];
            if (v < best || (v == best && ix < besti)) { best = v; besti = ix; }
        }
        g_idx[row0 + tid] = besti;
    }
}

// ---------------- 4) gather zq, write indices, accumulate loss ---------------
__global__ void vq_out(const float* __restrict__ z, const float* __restrict__ emb,
                       float* __restrict__ out_zq, float* __restrict__ out_idxf) {
    int t = blockIdx.x * blockDim.x + threadIdx.x;
    int nthreads = gridDim.x * blockDim.x;
    double s = 0.0;
    for (int e = t; e < NPTS * DDIM; e += nthreads) {
        int row = e >> 6, c = e & 63;
        float zv = z[e];
        float ev = emb[(size_t)g_idx[row] * DDIM + c];
        float r  = __fadd_rn(ev, -zv);              // fl(zq - z)
        if (out_zq) out_zq[e] = __fadd_rn(zv, r);   // fl(z + fl(zq - z))
        s += (double)__fmul_rn(r, r);               // fl((zq - z)^2)
    }
    if (out_idxf && t < NPTS) out_idxf[t] = (float)g_idx[t];
    __shared__ double sd[256];
    sd[threadIdx.x] = s;
    __syncthreads();
    for (int o = 128; o > 0; o >>= 1) {
        if (threadIdx.x < o) sd[threadIdx.x] += sd[threadIdx.x + o];
        __syncthreads();
    }
    if (threadIdx.x == 0) atomicAdd(&g_loss, sd[0]);
}

__global__ void vq_loss(float* __restrict__ out_loss) {
    float m = (float)g_loss / (float)(NPTS * DDIM);
    out_loss[0] = __fadd_rn(__fmul_rn(0.25f, m), m);
}

// ---------------- launch -----------------------------------------------------
extern "C" void kernel_launch(void* const* d_in, const int* in_sizes, int n_in,
                              void* d_out, int out_size) {
    const float* z   = (const float*)d_in[0];
    const float* emb = (const float*)d_in[1];
    if (n_in >= 2 && in_sizes[0] == KCODES * DDIM && in_sizes[1] == NPTS * DDIM) {
        const float* t = z; z = emb; emb = t;  // defensive swap
    }

    float* out = (float*)d_out;
    float* out_zq = nullptr; float* out_idxf = nullptr; float* out_loss = nullptr;
    const int NZ = NPTS * DDIM;
    if (out_size >= NZ + NPTS + 1) {           // [zq | min_ind | loss]
        out_zq = out; out_idxf = out + NZ; out_loss = out + NZ + NPTS;
    } else if (out_size == NZ) {
        out_zq = out;
    } else if (out_size == NPTS) {
        out_idxf = out;
    } else if (out_size == 1) {
        out_loss = out;
    } else {                                   // unknown: best effort zq
        out_zq = out;
    }

    float* zT; float* eT;
    cudaGetSymbolAddress((void**)&zT, g_zT);
    cudaGetSymbolAddress((void**)&eT, g_eT);
    cudaFuncSetAttribute(vq_main, cudaFuncAttributeMaxDynamicSharedMemorySize,
                         (2 * 64 * 128 + 256) * (int)sizeof(float));

    vq_norms<<<(NPTS + KCODES + 255) / 256, 256>>>(z, emb);
    vq_transpose<<<dim3(DDIM / 32, NPTS / 32), dim3(32, 8)>>>(z, zT, NPTS, DDIM);
    vq_transpose<<<dim3(DDIM / 32, KCODES / 32), dim3(32, 8)>>>(emb, eT, KCODES, DDIM);
    vq_main<<<NPTS / MT, 256, (2 * 64 * 128 + 256) * sizeof(float)>>>();
    vq_out<<<256, 256>>>(z, emb, out_zq, out_idxf);
    if (out_loss) vq_loss<<<1, 1>>>(out_loss);
}

// round 6
// speedup vs baseline: 1.3674x; 1.3674x over previous
#include <cuda_runtime.h>
#include <cuda_bf16.h>
#include <cstdint>

#define NPTS   32768
#define DDIM   64
#define KCODES 8192
#define KSPLIT 384
#define MROWS  256                 // rows per CTA
#define NT     128                 // codes per N tile
#define NTILES 64
#define KC     32                  // k per chunk
#define NCH    12                  // chunks per N tile
#define NSTEP  (NTILES * NCH)
#define AROW   768                 // bytes per A row (384 bf16)
#define ABYTES (MROWS * AROW)      // 196608
#define BBYTES (NT * KC * 2)       // 8192
#define SM_B0  ABYTES
#define SM_B1  (ABYTES + BBYTES)
#define SMEM_TOTAL (ABYTES + 2 * BBYTES)   // 212992 <= 227KB

__device__ __align__(256) __nv_bfloat16 g_A[(size_t)NPTS * KSPLIT];
__device__ __align__(256) __nv_bfloat16 g_B[(size_t)KCODES * KSPLIT];
__device__ float  g_zz[NPTS];
__device__ float  g_ee[KCODES];
__device__ int    g_idx[NPTS];
__device__ double g_loss;

// ---------------- helpers ----------------------------------------------------
__device__ __forceinline__ uint32_t smem_u32(const void* p) {
    uint32_t a;
    asm("{ .reg .u64 t; cvta.to.shared.u64 t, %1; cvt.u32.u64 %0, t; }" : "=r"(a) : "l"(p));
    return a;
}
__device__ __forceinline__ void cp16(uint32_t dst, const void* src) {
    asm volatile("cp.async.cg.shared.global [%0], [%1], 16;" :: "r"(dst), "l"(src) : "memory");
}
#define CP_COMMIT() asm volatile("cp.async.commit_group;" ::: "memory")
#define CP_WAIT0()  asm volatile("cp.async.wait_group 0;" ::: "memory")

#define LDMX4(r, addr) asm volatile( \
    "ldmatrix.sync.aligned.m8n8.x4.shared.b16 {%0,%1,%2,%3}, [%4];" \
    : "=r"((r)[0]), "=r"((r)[1]), "=r"((r)[2]), "=r"((r)[3]) : "r"(addr))

#define MMA(c, a, b0, b1) asm volatile( \
    "mma.sync.aligned.m16n8k16.row.col.f32.bf16.bf16.f32 " \
    "{%0,%1,%2,%3}, {%4,%5,%6,%7}, {%8,%9}, {%0,%1,%2,%3};" \
    : "+f"((c)[0]), "+f"((c)[1]), "+f"((c)[2]), "+f"((c)[3]) \
    : "r"((a)[0]), "r"((a)[1]), "r"((a)[2]), "r"((a)[3]), "r"(b0), "r"(b1))

// ---------------- 1) norms ----------------------------------------------------
__global__ void vq_norms(const float* __restrict__ z, const float* __restrict__ e) {
    int t = blockIdx.x * blockDim.x + threadIdx.x;
    if (t == 0) g_loss = 0.0;
    if (t < NPTS) {
        const float* p = z + (size_t)t * DDIM;
        float s = 0.f;
        for (int k = 0; k < DDIM; k++) s = __fadd_rn(s, __fmul_rn(p[k], p[k]));
        g_zz[t] = s;
    } else if (t < NPTS + KCODES) {
        const float* p = e + (size_t)(t - NPTS) * DDIM;
        float s = 0.f;
        for (int k = 0; k < DDIM; k++) s = __fadd_rn(s, __fmul_rn(p[k], p[k]));
        g_ee[t - NPTS] = s;
    }
}

// ---------------- 2) 3-limb bf16 split ---------------------------------------
// dot = [z1 z1 z2 z2 z1 z3] . [e1 e2 e1 e2 e3 e1]   (error ~2^-27 * |z||e|)
__global__ void vq_split(const float* __restrict__ z, const float* __restrict__ e) {
    int t = blockIdx.x * blockDim.x + threadIdx.x;
    if (t >= (NPTS + KCODES) * DDIM) return;
    bool isz = t < NPTS * DDIM;
    int u = isz ? t : t - NPTS * DDIM;
    float v = isz ? z[t] : e[u];
    __nv_bfloat16 b1 = __float2bfloat16(v);
    float r1 = v - __bfloat162float(b1);
    __nv_bfloat16 b2 = __float2bfloat16(r1);
    __nv_bfloat16 b3 = __float2bfloat16(r1 - __bfloat162float(b2));
    int row = u >> 6, k = u & 63;
    if (isz) {
        __nv_bfloat16* A = g_A + (size_t)row * KSPLIT;
        A[k] = b1; A[64 + k] = b1; A[128 + k] = b2;
        A[192 + k] = b2; A[256 + k] = b1; A[320 + k] = b3;
    } else {
        __nv_bfloat16* B = g_B + (size_t)row * KSPLIT;
        B[k] = b1; B[64 + k] = b2; B[128 + k] = b1;
        B[192 + k] = b2; B[256 + k] = b3; B[320 + k] = b1;
    }
}

// ---------------- 3) main: HMMA GEMM + fused argmin --------------------------
__global__ void __launch_bounds__(256, 1) vq_main() {
    extern __shared__ __align__(1024) char sm[];
    const uint32_t sbase = smem_u32(sm);
    const int tid = threadIdx.x, lane = tid & 31, wid = tid >> 5;
    const int wm = wid >> 1, wn = wid & 1;            // 4 x 2 warp grid
    const int row0 = blockIdx.x * MROWS;

    // A -> SMEM (swizzled), 48 granules/thread
    for (int q = 0; q < 48; q++) {
        int i = tid + 256 * q;
        int m = i / 48, g = i - m * 48;
        uint32_t dst = sbase + m * AROW + ((uint32_t)((g & ~7) | ((g ^ m) & 7)) << 4);
        cp16(dst, g_A + (size_t)(row0 + m) * KSPLIT + g * 8);
    }
    // B chunk 0 (ntile 0, kc 0)
    #pragma unroll
    for (int q = 0; q < 2; q++) {
        int i = tid + 256 * q;
        int n = i >> 2, g = i & 3;
        uint32_t dst = sbase + SM_B0 + n * 64 + ((uint32_t)((g ^ (n >> 1)) & 3) << 4);
        cp16(dst, g_B + (size_t)n * KSPLIT + g * 8);
    }
    CP_COMMIT();

    float bv[8]; int bi[8];
    #pragma unroll
    for (int r = 0; r < 8; r++) { bv[r] = 3.4e38f; bi[r] = 0; }
    float zz[8];
    #pragma unroll
    for (int mt = 0; mt < 4; mt++)
        #pragma unroll
        for (int h = 0; h < 2; h++)
            zz[mt * 2 + h] = g_zz[row0 + wm * 64 + mt * 16 + h * 8 + (lane >> 2)];

    float acc[4][8][4];

    for (int nt = 0; nt < NTILES; nt++) {
        #pragma unroll
        for (int mt = 0; mt < 4; mt++)
            #pragma unroll
            for (int c8 = 0; c8 < 8; c8++)
                #pragma unroll
                for (int c = 0; c < 4; c++) acc[mt][c8][c] = 0.f;

        for (int kc = 0; kc < NCH; kc++) {
            const int step = nt * NCH + kc;
            CP_WAIT0();
            __syncthreads();
            if (step + 1 < NSTEP) {                    // prefetch next chunk
                int s2 = step + 1, nt2 = s2 / NCH, kc2 = s2 - nt2 * NCH;
                uint32_t bb = sbase + ((s2 & 1) ? SM_B1 : SM_B0);
                const __nv_bfloat16* src = g_B + (size_t)nt2 * NT * KSPLIT + kc2 * KC;
                #pragma unroll
                for (int q = 0; q < 2; q++) {
                    int i = tid + 256 * q;
                    int n = i >> 2, g = i & 3;
                    cp16(bb + n * 64 + ((uint32_t)((g ^ (n >> 1)) & 3) << 4),
                         src + (size_t)n * KSPLIT + g * 8);
                }
                CP_COMMIT();
            }
            const uint32_t bbuf = sbase + ((step & 1) ? SM_B1 : SM_B0);
            #pragma unroll
            for (int ks = 0; ks < 2; ks++) {
                uint32_t a[4][4], b[4][4];
                const int agr = kc * 4 + ks * 2 + (lane >> 4);
                #pragma unroll
                for (int mt = 0; mt < 4; mt++) {
                    int m = wm * 64 + mt * 16 + (lane & 15);
                    uint32_t ad = sbase + m * AROW +
                        ((uint32_t)((agr & ~7) | ((agr ^ m) & 7)) << 4);
                    LDMX4(a[mt], ad);
                }
                const int bgr = ks * 2 + ((lane >> 3) & 1);
                #pragma unroll
                for (int np = 0; np < 4; np++) {
                    int n = wn * 64 + np * 16 + ((lane >> 4) & 1) * 8 + (lane & 7);
                    uint32_t bd = bbuf + n * 64 +
                        ((uint32_t)((bgr ^ (n >> 1)) & 3) << 4);
                    LDMX4(b[np], bd);
                }
                #pragma unroll
                for (int mt = 0; mt < 4; mt++)
                    #pragma unroll
                    for (int np = 0; np < 4; np++) {
                        MMA(acc[mt][2 * np],     a[mt], b[np][0], b[np][1]);
                        MMA(acc[mt][2 * np + 1], a[mt], b[np][2], b[np][3]);
                    }
            }
        }
        // epilogue: d = fl(fl(zz+ee) - 2*dot), strict < keeps lowest col
        #pragma unroll
        for (int c8 = 0; c8 < 8; c8++) {
            const int col = nt * NT + wn * 64 + c8 * 8 + 2 * (lane & 3);
            float2 e2 = *(const float2*)&g_ee[col];
            #pragma unroll
            for (int mt = 0; mt < 4; mt++)
                #pragma unroll
                for (int h = 0; h < 2; h++) {
                    const int r = mt * 2 + h;
                    float d0 = __fmaf_rn(-2.f, acc[mt][c8][2 * h],
                                         __fadd_rn(zz[r], e2.x));
                    float d1 = __fmaf_rn(-2.f, acc[mt][c8][2 * h + 1],
                                         __fadd_rn(zz[r], e2.y));
                    if (d0 < bv[r]) { bv[r] = d0; bi[r] = col; }
                    if (d1 < bv[r]) { bv[r] = d1; bi[r] = col + 1; }
                }
        }
    }

    // reduce: quad shfl (tie -> lower index), then across the 2 warp_n groups
    CP_WAIT0();
    __syncthreads();
    float* rv = (float*)(sm + SM_B0);
    int*   ri = (int*)(sm + SM_B0 + 4096);
    #pragma unroll
    for (int r = 0; r < 8; r++) {
        float v = bv[r]; int ix = bi[r];
        #pragma unroll
        for (int off = 1; off < 4; off <<= 1) {
            float ov = __shfl_xor_sync(0xffffffffu, v, off);
            int   oi = __shfl_xor_sync(0xffffffffu, ix, off);
            if (ov < v || (ov == v && oi < ix)) { v = ov; ix = oi; }
        }
        if ((lane & 3) == 0) {
            int row_l = wm * 64 + (r >> 1) * 16 + (r & 1) * 8 + (lane >> 2);
            rv[row_l * 2 + wn] = v; ri[row_l * 2 + wn] = ix;
        }
    }
    __syncthreads();
    if (tid < MROWS) {
        float v0 = rv[tid * 2], v1 = rv[tid * 2 + 1];
        int   i0 = ri[tid * 2], i1 = ri[tid * 2 + 1];
        bool take1 = (v1 < v0) || (v1 == v0 && i1 < i0);
        g_idx[row0 + tid] = take1 ? i1 : i0;
    }
}

// ---------------- 4) gather + loss -------------------------------------------
__global__ void vq_out(const float* __restrict__ z, const float* __restrict__ emb,
                       float* __restrict__ out_zq, float* __restrict__ out_idxf) {
    int t = blockIdx.x * blockDim.x + threadIdx.x;
    int nth = gridDim.x * blockDim.x;
    double s = 0.0;
    for (int e = t; e < NPTS * DDIM; e += nth) {
        int row = e >> 6, c = e & 63;
        float zv = z[e];
        float ev = emb[(size_t)g_idx[row] * DDIM + c];
        float r  = __fadd_rn(ev, -zv);
        if (out_zq) out_zq[e] = __fadd_rn(zv, r);
        s += (double)__fmul_rn(r, r);
    }
    if (out_idxf && t < NPTS) out_idxf[t] = (float)g_idx[t];
    __shared__ double sd[256];
    sd[threadIdx.x] = s;
    __syncthreads();
    for (int o = 128; o > 0; o >>= 1) {
        if (threadIdx.x < o) sd[threadIdx.x] += sd[threadIdx.x + o];
        __syncthreads();
    }
    if (threadIdx.x == 0) atomicAdd(&g_loss, sd[0]);
}

__global__ void vq_loss(float* __restrict__ out_loss) {
    float m = (float)g_loss / (float)(NPTS * DDIM);
    out_loss[0] = __fadd_rn(__fmul_rn(0.25f, m), m);
}

// ---------------- launch -----------------------------------------------------
extern "C" void kernel_launch(void* const* d_in, const int* in_sizes, int n_in,
                              void* d_out, int out_size) {
    const float* z   = (const float*)d_in[0];
    const float* emb = (const float*)d_in[1];
    if (n_in >= 2 && in_sizes[0] == KCODES * DDIM && in_sizes[1] == NPTS * DDIM) {
        const float* t = z; z = emb; emb = t;
    }
    float* out = (float*)d_out;
    float* out_zq = nullptr; float* out_idxf = nullptr; float* out_loss = nullptr;
    const int NZ = NPTS * DDIM;
    if (out_size >= NZ + NPTS + 1) { out_zq = out; out_idxf = out + NZ; out_loss = out + NZ + NPTS; }
    else if (out_size == NZ)   { out_zq = out; }
    else if (out_size == NPTS) { out_idxf = out; }
    else if (out_size == 1)    { out_loss = out; }
    else                       { out_zq = out; }

    cudaFuncSetAttribute(vq_main, cudaFuncAttributeMaxDynamicSharedMemorySize, SMEM_TOTAL);

    vq_norms<<<(NPTS + KCODES + 255) / 256, 256>>>(z, emb);
    vq_split<<<((NPTS + KCODES) * DDIM + 255) / 256, 256>>>(z, emb);
    vq_main<<<NPTS / MROWS, 256, SMEM_TOTAL>>>();
    vq_out<<<256, 256>>>(z, emb, out_zq, out_idxf);
    if (out_loss) vq_loss<<<1, 1>>>(out_loss);
}

// round 7
// speedup vs baseline: 2.5083x; 1.8343x over previous
#include <cuda_runtime.h>
#include <cuda_fp16.h>
#include <cstdint>

#define NPTS   32768
#define DDIM   64
#define KCODES 8192
#define KK     192
#define AROW   384                  // bytes per row (192 fp16)
#define MROWS  256
#define ABYTES (MROWS * AROW)       // 98304
#define CHROWS 64                   // codes per chunk
#define CHBYTES (CHROWS * AROW)     // 24576
#define NCHUNK (KCODES / CHROWS)    // 128
#define SMEM_TOTAL (ABYTES + 4 * CHBYTES)   // 196608

__device__ __align__(256) __half g_A[(size_t)NPTS * KK];
__device__ __align__(256) __half g_B[(size_t)KCODES * KK];
__device__ float  g_zz[NPTS];
__device__ float  g_ee[KCODES];
__device__ int    g_idx[NPTS];
__device__ double g_loss;

__device__ __forceinline__ uint32_t smem_u32(const void* p) {
    uint32_t a;
    asm("{ .reg .u64 t; cvta.to.shared.u64 t, %1; cvt.u32.u64 %0, t; }" : "=r"(a) : "l"(p));
    return a;
}
__device__ __forceinline__ void cp16(uint32_t dst, const void* src) {
    asm volatile("cp.async.cg.shared.global [%0], [%1], 16;" :: "r"(dst), "l"(src) : "memory");
}
#define CP_COMMIT() asm volatile("cp.async.commit_group;" ::: "memory")
#define CP_WAIT(n)  asm volatile("cp.async.wait_group %0;" :: "n"(n) : "memory")

#define LDMX4(r, addr) asm volatile( \
    "ldmatrix.sync.aligned.m8n8.x4.shared.b16 {%0,%1,%2,%3}, [%4];" \
    : "=r"((r)[0]), "=r"((r)[1]), "=r"((r)[2]), "=r"((r)[3]) : "r"(addr))

#define MMA(c, a, b0, b1) asm volatile( \
    "mma.sync.aligned.m16n8k16.row.col.f32.f16.f16.f32 " \
    "{%0,%1,%2,%3}, {%4,%5,%6,%7}, {%8,%9}, {%0,%1,%2,%3};" \
    : "+f"((c)[0]), "+f"((c)[1]), "+f"((c)[2]), "+f"((c)[3]) \
    : "r"((a)[0]), "r"((a)[1]), "r"((a)[2]), "r"((a)[3]), "r"(b0), "r"(b1))

// ---------------- 1) norms ----------------------------------------------------
__global__ void vq_norms(const float* __restrict__ z, const float* __restrict__ e) {
    int t = blockIdx.x * blockDim.x + threadIdx.x;
    if (t == 0) g_loss = 0.0;
    if (t < NPTS) {
        const float* p = z + (size_t)t * DDIM;
        float s = 0.f;
        for (int k = 0; k < DDIM; k++) s = __fadd_rn(s, __fmul_rn(p[k], p[k]));
        g_zz[t] = s;
    } else if (t < NPTS + KCODES) {
        const float* p = e + (size_t)(t - NPTS) * DDIM;
        float s = 0.f;
        for (int k = 0; k < DDIM; k++) s = __fadd_rn(s, __fmul_rn(p[k], p[k]));
        g_ee[t - NPTS] = s;
    }
}

// ---------------- 2) 2-limb fp16 split (scaled) ------------------------------
// A row: [a1 a1 a2] of z*64 ; B row: [b1 b2 b1] of e*512.
// sum = 2^15 * (z1e1 + z1e2 + z2e1); dropped z2e2 ~ 2^-24 |z||e|.
__global__ void vq_split(const float* __restrict__ z, const float* __restrict__ e) {
    int t = blockIdx.x * blockDim.x + threadIdx.x;
    if (t >= (NPTS + KCODES) * DDIM) return;
    bool isz = t < NPTS * DDIM;
    int u = isz ? t : t - NPTS * DDIM;
    int row = u >> 6, k = u & 63;
    if (isz) {
        float v = z[t] * 64.f;
        __half a1 = __float2half_rn(v);
        __half a2 = __float2half_rn(v - __half2float(a1));
        __half* A = g_A + (size_t)row * KK;
        A[k] = a1; A[64 + k] = a1; A[128 + k] = a2;
    } else {
        float v = e[u] * 512.f;
        __half b1 = __float2half_rn(v);
        __half b2 = __float2half_rn(v - __half2float(b1));
        __half* B = g_B + (size_t)row * KK;
        B[k] = b1; B[64 + k] = b2; B[128 + k] = b1;
    }
}

// ---------------- 3) main: HMMA GEMM + fused argmin --------------------------
__global__ void __launch_bounds__(256, 1) vq_main() {
    extern __shared__ __align__(1024) char sm[];
    const uint32_t sbase = smem_u32(sm);
    const int tid = threadIdx.x, lane = tid & 31, wid = tid >> 5;
    const int wm = wid >> 1, wn = wid & 1;          // 4(M) x 2(N) warp grid
    const int row0 = blockIdx.x * MROWS;

    // A -> SMEM swizzled: 6144 granules, 24/thread
    #pragma unroll
    for (int q = 0; q < 24; q++) {
        int i = tid + 256 * q;
        int m = i / 24, g = i - m * 24;
        uint32_t dst = sbase + m * AROW + (((g & ~7) | ((g ^ m) & 7)) << 4);
        cp16(dst, (const char*)g_A + (size_t)(row0 + m) * AROW + g * 16);
    }
    CP_COMMIT();

    auto load_chunk = [&](int c, int s) {
        const char* src = (const char*)g_B + (size_t)c * CHROWS * AROW;
        uint32_t d0 = sbase + ABYTES + s * CHBYTES;
        #pragma unroll
        for (int q = 0; q < 6; q++) {
            int i = tid + 256 * q;                  // 0..1535
            int n = i / 24, g = i - n * 24;
            cp16(d0 + n * AROW + (((g & ~7) | ((g ^ n) & 7)) << 4),
                 src + (size_t)n * AROW + g * 16);
        }
        CP_COMMIT();
    };
    load_chunk(0, 0);
    load_chunk(1, 1);

    float zz[8];
    #pragma unroll
    for (int mt = 0; mt < 4; mt++)
        #pragma unroll
        for (int h = 0; h < 2; h++)
            zz[mt * 2 + h] = g_zz[row0 + wm * 64 + mt * 16 + h * 8 + (lane >> 2)];
    float bv[8]; int bi[8];
    #pragma unroll
    for (int r = 0; r < 8; r++) { bv[r] = 3.4e38f; bi[r] = 0; }

    const uint32_t abase = sbase + (wm * 64 + (lane & 15)) * AROW;
    const uint32_t nbase = (wn * 32 + ((lane >> 4) & 1) * 8 + (lane & 7)) * AROW;

    for (int c = 0; c < NCHUNK; c++) {
        if (c + 2 < NCHUNK) load_chunk(c + 2, (c + 2) & 3);
        CP_WAIT(2);
        __syncthreads();
        const uint32_t bbase = sbase + ABYTES + (c & 3) * CHBYTES + nbase;

        float acc[4][4][4];
        #pragma unroll
        for (int mt = 0; mt < 4; mt++)
            #pragma unroll
            for (int c8 = 0; c8 < 4; c8++)
                #pragma unroll
                for (int x = 0; x < 4; x++) acc[mt][c8][x] = 0.f;

        #pragma unroll
        for (int kc = 0; kc < 12; kc++) {
            uint32_t a[4][4], b[2][4];
            const int agr = kc * 2 + (lane >> 4);
            const uint32_t aoff = ((agr & ~7) | ((agr ^ (lane & 7)) & 7)) << 4;
            #pragma unroll
            for (int mt = 0; mt < 4; mt++)
                LDMX4(a[mt], abase + mt * (16 * AROW) + aoff);
            const int bgr = kc * 2 + ((lane >> 3) & 1);
            const uint32_t boff = ((bgr & ~7) | ((bgr ^ (lane & 7)) & 7)) << 4;
            #pragma unroll
            for (int np = 0; np < 2; np++)
                LDMX4(b[np], bbase + np * (16 * AROW) + boff);
            #pragma unroll
            for (int mt = 0; mt < 4; mt++)
                #pragma unroll
                for (int np = 0; np < 2; np++) {
                    MMA(acc[mt][2 * np],     a[mt], b[np][0], b[np][1]);
                    MMA(acc[mt][2 * np + 1], a[mt], b[np][2], b[np][3]);
                }
        }
        // d = fl( fl(zz+ee) - 2^-14 * acc ), strict < keeps lowest index
        #pragma unroll
        for (int c8 = 0; c8 < 4; c8++) {
            const int col = c * 64 + wn * 32 + c8 * 8 + 2 * (lane & 3);
            float2 e2 = *(const float2*)&g_ee[col];
            #pragma unroll
            for (int mt = 0; mt < 4; mt++)
                #pragma unroll
                for (int h = 0; h < 2; h++) {
                    const int r = mt * 2 + h;
                    float d0 = __fmaf_rn(-6.103515625e-05f, acc[mt][c8][2 * h],
                                         __fadd_rn(zz[r], e2.x));
                    float d1 = __fmaf_rn(-6.103515625e-05f, acc[mt][c8][2 * h + 1],
                                         __fadd_rn(zz[r], e2.y));
                    if (d0 < bv[r]) { bv[r] = d0; bi[r] = col; }
                    if (d1 < bv[r]) { bv[r] = d1; bi[r] = col + 1; }
                }
        }
    }

    CP_WAIT(0);
    __syncthreads();
    float* rv = (float*)(sm + ABYTES);
    int*   ri = (int*)(sm + ABYTES + 2048);
    #pragma unroll
    for (int r = 0; r < 8; r++) {
        float v = bv[r]; int ix = bi[r];
        #pragma unroll
        for (int off = 1; off < 4; off <<= 1) {
            float ov = __shfl_xor_sync(0xffffffffu, v, off);
            int   oi = __shfl_xor_sync(0xffffffffu, ix, off);
            if (ov < v || (ov == v && oi < ix)) { v = ov; ix = oi; }
        }
        if ((lane & 3) == 0) {
            int row_l = wm * 64 + (r >> 1) * 16 + (r & 1) * 8 + (lane >> 2);
            rv[row_l * 2 + wn] = v; ri[row_l * 2 + wn] = ix;
        }
    }
    __syncthreads();
    if (tid < MROWS) {
        float v0 = rv[tid * 2], v1 = rv[tid * 2 + 1];
        int   i0 = ri[tid * 2], i1 = ri[tid * 2 + 1];
        bool take1 = (v1 < v0) || (v1 == v0 && i1 < i0);
        g_idx[row0 + tid] = take1 ? i1 : i0;
    }
}

// ---------------- 4) gather + loss -------------------------------------------
__global__ void vq_out(const float* __restrict__ z, const float* __restrict__ emb,
                       float* __restrict__ out_zq, float* __restrict__ out_idxf) {
    int t = blockIdx.x * blockDim.x + threadIdx.x;
    int nth = gridDim.x * blockDim.x;
    double s = 0.0;
    for (int e4 = t; e4 < NPTS * DDIM / 4; e4 += nth) {
        int row = e4 >> 4;
        float4 zv = ((const float4*)z)[e4];
        float4 ev = *(const float4*)(emb + (size_t)g_idx[row] * DDIM + (e4 & 15) * 4);
        float rx = __fadd_rn(ev.x, -zv.x), ry = __fadd_rn(ev.y, -zv.y);
        float rz = __fadd_rn(ev.z, -zv.z), rw = __fadd_rn(ev.w, -zv.w);
        if (out_zq) {
            float4 o;
            o.x = __fadd_rn(zv.x, rx); o.y = __fadd_rn(zv.y, ry);
            o.z = __fadd_rn(zv.z, rz); o.w = __fadd_rn(zv.w, rw);
            ((float4*)out_zq)[e4] = o;
        }
        s += (double)__fmul_rn(rx, rx) + (double)__fmul_rn(ry, ry)
           + (double)__fmul_rn(rz, rz) + (double)__fmul_rn(rw, rw);
    }
    if (out_idxf && t < NPTS) out_idxf[t] = (float)g_idx[t];
    __shared__ double sd[256];
    sd[threadIdx.x] = s;
    __syncthreads();
    for (int o = 128; o > 0; o >>= 1) {
        if (threadIdx.x < o) sd[threadIdx.x] += sd[threadIdx.x + o];
        __syncthreads();
    }
    if (threadIdx.x == 0) atomicAdd(&g_loss, sd[0]);
}

__global__ void vq_loss(float* __restrict__ out_loss) {
    float m = (float)g_loss / (float)(NPTS * DDIM);
    out_loss[0] = __fadd_rn(__fmul_rn(0.25f, m), m);
}

// ---------------- launch -----------------------------------------------------
extern "C" void kernel_launch(void* const* d_in, const int* in_sizes, int n_in,
                              void* d_out, int out_size) {
    const float* z   = (const float*)d_in[0];
    const float* emb = (const float*)d_in[1];
    if (n_in >= 2 && in_sizes[0] == KCODES * DDIM && in_sizes[1] == NPTS * DDIM) {
        const float* t = z; z = emb; emb = t;
    }
    float* out = (float*)d_out;
    float* out_zq = nullptr; float* out_idxf = nullptr; float* out_loss = nullptr;
    const int NZ = NPTS * DDIM;
    if (out_size >= NZ + NPTS + 1) { out_zq = out; out_idxf = out + NZ; out_loss = out + NZ + NPTS; }
    else if (out_size == NZ)   { out_zq = out; }
    else if (out_size == NPTS) { out_idxf = out; }
    else if (out_size == 1)    { out_loss = out; }
    else                       { out_zq = out; }

    cudaFuncSetAttribute(vq_main, cudaFuncAttributeMaxDynamicSharedMemorySize, SMEM_TOTAL);

    vq_norms<<<(NPTS + KCODES + 255) / 256, 256>>>(z, emb);
    vq_split<<<((NPTS + KCODES) * DDIM + 255) / 256, 256>>>(z, emb);
    vq_main<<<NPTS / MROWS, 256, SMEM_TOTAL>>>();
    vq_out<<<512, 256>>>(z, emb, out_zq, out_idxf);
    if (out_loss) vq_loss<<<1, 1>>>(out_loss);
}

// round 8
// speedup vs baseline: 4.7782x; 1.9049x over previous
#include <cuda_runtime.h>
#include <cuda_fp16.h>
#include <cstdint>
#include <cfloat>

#define NPTS   32768
#define DDIM   64
#define KCODES 8192
#define MROWS  128
#define AROW   128                  // bytes per row (64 fp16)
#define ABYTES (MROWS * AROW)       // 16384
#define CHROWS 64
#define CHBYTES (CHROWS * AROW)     // 8192
#define NCHUNK (KCODES / CHROWS)    // 128
#define SMEM_TOTAL (ABYTES + 4 * CHBYTES)   // 49152
#define USCALE 6.103515625e-05f     // 2^-14 : acc -> 2*dot

__device__ __align__(256) __half g_A[(size_t)NPTS * DDIM];
__device__ __align__(256) __half g_B[(size_t)KCODES * DDIM];
__device__ float  g_zz[NPTS];
__device__ float  g_ee[KCODES];
__device__ int    g_eemax_i;
__device__ int    g_cand[NPTS][16];
__device__ int    g_ccnt[NPTS];
__device__ int    g_idx[NPTS];
__device__ double g_loss;

__device__ __forceinline__ uint32_t smem_u32(const void* p) {
    uint32_t a;
    asm("{ .reg .u64 t; cvta.to.shared.u64 t, %1; cvt.u32.u64 %0, t; }" : "=r"(a) : "l"(p));
    return a;
}
__device__ __forceinline__ void cp16(uint32_t dst, const void* src) {
    asm volatile("cp.async.cg.shared.global [%0], [%1], 16;" :: "r"(dst), "l"(src) : "memory");
}
#define CP_COMMIT() asm volatile("cp.async.commit_group;" ::: "memory")
#define CP_WAIT(n)  asm volatile("cp.async.wait_group %0;" :: "n"(n) : "memory")

#define LDMX4(r, addr) asm volatile( \
    "ldmatrix.sync.aligned.m8n8.x4.shared.b16 {%0,%1,%2,%3}, [%4];" \
    : "=r"((r)[0]), "=r"((r)[1]), "=r"((r)[2]), "=r"((r)[3]) : "r"(addr))

#define MMA(c, a, b0, b1) asm volatile( \
    "mma.sync.aligned.m16n8k16.row.col.f32.f16.f16.f32 " \
    "{%0,%1,%2,%3}, {%4,%5,%6,%7}, {%8,%9}, {%0,%1,%2,%3};" \
    : "+f"((c)[0]), "+f"((c)[1]), "+f"((c)[2]), "+f"((c)[3]) \
    : "r"((a)[0]), "r"((a)[1]), "r"((a)[2]), "r"((a)[3]), "r"(b0), "r"(b1))

// ---------------- 0) init -----------------------------------------------------
__global__ void vq_init() { g_loss = 0.0; g_eemax_i = 0; }

// ---------------- 1) norms (+ global max ||e||^2) -----------------------------
__global__ void vq_norms(const float* __restrict__ z, const float* __restrict__ e) {
    int t = blockIdx.x * blockDim.x + threadIdx.x;
    if (t < NPTS) {
        const float* p = z + (size_t)t * DDIM;
        float s = 0.f;
        for (int k = 0; k < DDIM; k++) s = __fadd_rn(s, __fmul_rn(p[k], p[k]));
        g_zz[t] = s;
    } else if (t < NPTS + KCODES) {
        const float* p = e + (size_t)(t - NPTS) * DDIM;
        float s = 0.f;
        for (int k = 0; k < DDIM; k++) s = __fadd_rn(s, __fmul_rn(p[k], p[k]));
        g_ee[t - NPTS] = s;
        atomicMax(&g_eemax_i, __float_as_int(s));
    }
}

// ---------------- 2) single-limb fp16 quantize (scaled) -----------------------
__global__ void vq_split(const float* __restrict__ z, const float* __restrict__ e) {
    int t = blockIdx.x * blockDim.x + threadIdx.x;
    if (t < NPTS * DDIM) {
        g_A[t] = __float2half_rn(z[t] * 64.f);
    } else if (t < (NPTS + KCODES) * DDIM) {
        int u = t - NPTS * DDIM;
        g_B[u] = __float2half_rn(e[u] * 512.f);
    }
}

// ---------------- 3) pass 1: approx GEMM + best-2 candidate scan --------------
__global__ void __launch_bounds__(256, 2) vq_main() {
    extern __shared__ __align__(1024) char sm[];
    const uint32_t sbase = smem_u32(sm);
    const int tid = threadIdx.x, lane = tid & 31, wid = tid >> 5;
    const int wm = wid >> 1, wn = wid & 1;          // 4(M) x 2(N) warps
    const int row0 = blockIdx.x * MROWS;

    // A -> SMEM swizzled: 1024 granules, 4/thread
    #pragma unroll
    for (int q = 0; q < 4; q++) {
        int i = tid + 256 * q;
        int m = i >> 3, g = i & 7;
        cp16(sbase + m * AROW + ((g ^ (m & 7)) << 4),
             (const char*)g_A + (size_t)(row0 + m) * AROW + g * 16);
    }
    CP_COMMIT();

    auto load_chunk = [&](int c, int s) {
        const char* src = (const char*)g_B + (size_t)c * CHROWS * AROW;
        uint32_t d0 = sbase + ABYTES + s * CHBYTES;
        #pragma unroll
        for (int q = 0; q < 2; q++) {
            int i = tid + 256 * q;
            int n = i >> 3, g = i & 7;
            cp16(d0 + n * AROW + ((g ^ (n & 7)) << 4),
                 src + (size_t)n * AROW + g * 16);
        }
        CP_COMMIT();
    };
    load_chunk(0, 0);
    load_chunk(1, 1);

    float v1[4], v2[4]; int i1[4], i2[4];
    #pragma unroll
    for (int r = 0; r < 4; r++) { v1[r] = -FLT_MAX; v2[r] = -FLT_MAX; i1[r] = 0; i2[r] = 0; }

    const uint32_t abase = sbase + (wm * 32 + (lane & 15)) * AROW;
    const uint32_t nbase = (wn * 32 + ((lane >> 4) & 1) * 8 + (lane & 7)) * AROW;

    for (int c = 0; c < NCHUNK; c++) {
        if (c + 2 < NCHUNK) load_chunk(c + 2, (c + 2) & 3);
        CP_WAIT(2);
        __syncthreads();
        const uint32_t bbase = sbase + ABYTES + (c & 3) * CHBYTES + nbase;

        float acc[2][4][4];
        #pragma unroll
        for (int mt = 0; mt < 2; mt++)
            #pragma unroll
            for (int c8 = 0; c8 < 4; c8++)
                #pragma unroll
                for (int x = 0; x < 4; x++) acc[mt][c8][x] = 0.f;

        #pragma unroll
        for (int kc = 0; kc < 4; kc++) {
            uint32_t a[2][4], b[2][4];
            const int agr = kc * 2 + (lane >> 4);
            #pragma unroll
            for (int mt = 0; mt < 2; mt++) {
                int m = wm * 32 + mt * 16 + (lane & 15);
                LDMX4(a[mt], abase + mt * (16 * AROW) + ((agr ^ (m & 7)) << 4));
            }
            const int bgr = kc * 2 + ((lane >> 3) & 1);
            #pragma unroll
            for (int np = 0; np < 2; np++) {
                int n = wn * 32 + np * 16 + ((lane >> 4) & 1) * 8 + (lane & 7);
                LDMX4(b[np], bbase + np * (16 * AROW) + ((bgr ^ (n & 7)) << 4));
            }
            #pragma unroll
            for (int mt = 0; mt < 2; mt++)
                #pragma unroll
                for (int np = 0; np < 2; np++) {
                    MMA(acc[mt][2 * np],     a[mt], b[np][0], b[np][1]);
                    MMA(acc[mt][2 * np + 1], a[mt], b[np][2], b[np][3]);
                }
        }
        // scan: u = 2^-14*acc - ee ; keep top-2 per row (strict >, lowest idx first)
        #pragma unroll
        for (int c8 = 0; c8 < 4; c8++) {
            const int col = c * 64 + wn * 32 + c8 * 8 + 2 * (lane & 3);
            float2 e2 = *(const float2*)&g_ee[col];
            #pragma unroll
            for (int mt = 0; mt < 2; mt++)
                #pragma unroll
                for (int h = 0; h < 2; h++) {
                    const int r = mt * 2 + h;
                    float u0 = __fmaf_rn(USCALE, acc[mt][c8][2 * h],     -e2.x);
                    float u1 = __fmaf_rn(USCALE, acc[mt][c8][2 * h + 1], -e2.y);
                    if (u0 > v2[r]) {
                        if (u0 > v1[r]) { v2[r] = v1[r]; i2[r] = i1[r]; v1[r] = u0; i1[r] = col; }
                        else            { v2[r] = u0; i2[r] = col; }
                    }
                    if (u1 > v2[r]) {
                        if (u1 > v1[r]) { v2[r] = v1[r]; i2[r] = i1[r]; v1[r] = u1; i1[r] = col + 1; }
                        else            { v2[r] = u1; i2[r] = col + 1; }
                    }
                }
        }
    }

    CP_WAIT(0);
    __syncthreads();
    float* rv = (float*)(sm + ABYTES);          // [128][16]
    int*   ri = (int*)(sm + ABYTES + 8192);
    #pragma unroll
    for (int r = 0; r < 4; r++) {
        int row_l = wm * 32 + (r >> 1) * 16 + (r & 1) * 8 + (lane >> 2);
        int slot = wn * 8 + (lane & 3) * 2;
        rv[row_l * 16 + slot] = v1[r];     ri[row_l * 16 + slot] = i1[r];
        rv[row_l * 16 + slot + 1] = v2[r]; ri[row_l * 16 + slot + 1] = i2[r];
    }
    __syncthreads();
    if (tid < MROWS) {
        float vmax = -FLT_MAX;
        #pragma unroll
        for (int s = 0; s < 16; s++) vmax = fmaxf(vmax, rv[tid * 16 + s]);
        float eemax = __int_as_float(g_eemax_i);
        float W = 1.46484375e-3f * sqrtf(g_zz[row0 + tid] * eemax) + 5e-5f;
        float thr = vmax - W;
        int cnt = 0;
        #pragma unroll
        for (int s = 0; s < 16; s++)
            if (rv[tid * 16 + s] >= thr && cnt < 16)
                g_cand[row0 + tid][cnt++] = ri[tid * 16 + s];
        g_ccnt[row0 + tid] = cnt;
    }
}

// ---------------- 4) pass 2: exact refine of survivors ------------------------
__global__ void vq_refine(const float* __restrict__ z, const float* __restrict__ e) {
    int row = blockIdx.x * 8 + (threadIdx.x >> 5);
    int lane = threadIdx.x & 31;
    if (row >= NPTS) return;
    int cnt = g_ccnt[row];
    int besti = g_cand[row][0];
    if (cnt > 1) {
        float zv1 = z[(size_t)row * DDIM + lane];
        float zv2 = z[(size_t)row * DDIM + 32 + lane];
        float zzv = g_zz[row];
        float bd = FLT_MAX; besti = 0x7fffffff;
        for (int t = 0; t < cnt; t++) {
            int idx = g_cand[row][t];
            float p = __fmaf_rn(zv2, e[(size_t)idx * DDIM + 32 + lane],
                                __fmul_rn(zv1, e[(size_t)idx * DDIM + lane]));
            #pragma unroll
            for (int off = 16; off; off >>= 1)
                p += __shfl_xor_sync(0xffffffffu, p, off);
            float d = __fmaf_rn(-2.f, p, __fadd_rn(zzv, g_ee[idx]));
            if (d < bd || (d == bd && idx < besti)) { bd = d; besti = idx; }
        }
    }
    if (lane == 0) g_idx[row] = besti;
}

// ---------------- 5) gather + loss -------------------------------------------
__global__ void vq_out(const float* __restrict__ z, const float* __restrict__ emb,
                       float* __restrict__ out_zq, float* __restrict__ out_idxf) {
    int t = blockIdx.x * blockDim.x + threadIdx.x;
    int nth = gridDim.x * blockDim.x;
    double s = 0.0;
    for (int e4 = t; e4 < NPTS * DDIM / 4; e4 += nth) {
        int row = e4 >> 4;
        float4 zv = ((const float4*)z)[e4];
        float4 ev = *(const float4*)(emb + (size_t)g_idx[row] * DDIM + (e4 & 15) * 4);
        float rx = __fadd_rn(ev.x, -zv.x), ry = __fadd_rn(ev.y, -zv.y);
        float rz = __fadd_rn(ev.z, -zv.z), rw = __fadd_rn(ev.w, -zv.w);
        if (out_zq) {
            float4 o;
            o.x = __fadd_rn(zv.x, rx); o.y = __fadd_rn(zv.y, ry);
            o.z = __fadd_rn(zv.z, rz); o.w = __fadd_rn(zv.w, rw);
            ((float4*)out_zq)[e4] = o;
        }
        s += (double)__fmul_rn(rx, rx) + (double)__fmul_rn(ry, ry)
           + (double)__fmul_rn(rz, rz) + (double)__fmul_rn(rw, rw);
    }
    if (out_idxf && t < NPTS) out_idxf[t] = (float)g_idx[t];
    __shared__ double sd[256];
    sd[threadIdx.x] = s;
    __syncthreads();
    for (int o = 128; o > 0; o >>= 1) {
        if (threadIdx.x < o) sd[threadIdx.x] += sd[threadIdx.x + o];
        __syncthreads();
    }
    if (threadIdx.x == 0) atomicAdd(&g_loss, sd[0]);
}

__global__ void vq_loss(float* __restrict__ out_loss) {
    float m = (float)g_loss / (float)(NPTS * DDIM);
    out_loss[0] = __fadd_rn(__fmul_rn(0.25f, m), m);
}

// ---------------- launch -----------------------------------------------------
extern "C" void kernel_launch(void* const* d_in, const int* in_sizes, int n_in,
                              void* d_out, int out_size) {
    const float* z   = (const float*)d_in[0];
    const float* emb = (const float*)d_in[1];
    if (n_in >= 2 && in_sizes[0] == KCODES * DDIM && in_sizes[1] == NPTS * DDIM) {
        const float* t = z; z = emb; emb = t;
    }
    float* out = (float*)d_out;
    float* out_zq = nullptr; float* out_idxf = nullptr; float* out_loss = nullptr;
    const int NZ = NPTS * DDIM;
    if (out_size >= NZ + NPTS + 1) { out_zq = out; out_idxf = out + NZ; out_loss = out + NZ + NPTS; }
    else if (out_size == NZ)   { out_zq = out; }
    else if (out_size == NPTS) { out_idxf = out; }
    else if (out_size == 1)    { out_loss = out; }
    else                       { out_zq = out; }

    cudaFuncSetAttribute(vq_main, cudaFuncAttributeMaxDynamicSharedMemorySize, SMEM_TOTAL);

    vq_init<<<1, 1>>>();
    vq_norms<<<(NPTS + KCODES + 255) / 256, 256>>>(z, emb);
    vq_split<<<((NPTS + KCODES) * DDIM + 255) / 256, 256>>>(z, emb);
    vq_main<<<NPTS / MROWS, 256, SMEM_TOTAL>>>();
    vq_refine<<<NPTS / 8, 256>>>(z, emb);
    vq_out<<<512, 256>>>(z, emb, out_zq, out_idxf);
    if (out_loss) vq_loss<<<1, 1>>>(out_loss);
}